// round 6
// baseline (speedup 1.0000x reference)
#include <cuda_runtime.h>
#include <math.h>

#define NB 2
#define NC 21
#define NCP 11           // channel pairs (last padded)
#define PP 4096
#define KS 71
#define KR 35
#define KSPL 32
#define KCH 128          // 4096 / KSPL
#define GEMM_CTAS (NB * 8 * KSPL)   // 512: 8 rowblocks x 32 kslices x 2 batches
#define CONV_CTAS (NB * NC)

// ---------------- scratch (static device globals; no allocation) ----------------
__device__ float g_K[(size_t)NB * PP * PP];          // 134 MB fp32, symmetric
__device__ float g_feat[NB * 5 * PP];
__device__ float g_h[NB * PP];
__device__ float g_U[NB * NC * PP];
__device__ float g_q[NB * NC * PP];                  // q, channel-major (conv reads this)
__device__ float2 g_qpair[NB * NCP * PP];            // q packed by channel pair (gemm reads)
__device__ float g_part[NB * NC * KSPL * PP];        // gemm partials (22 MB)
__device__ float g_qbf[NB * NC * PP];                // reduced bilateral message
__device__ float g_qsf[NB * NC * PP];                // spatial conv result
__device__ float g_g1d[KS];

// ---------------- packed f32x2 FMA: acc.x += bx*cx, acc.y += by*cy ----------------
__device__ __forceinline__ void fma2(float2& a, float bx, float by, float cx, float cy) {
    float2 b = make_float2(bx, by);
    float2 c = make_float2(cx, cy);
    unsigned long long* pa = reinterpret_cast<unsigned long long*>(&a);
    unsigned long long bb = *reinterpret_cast<unsigned long long*>(&b);
    unsigned long long cc = *reinterpret_cast<unsigned long long*>(&c);
    asm("fma.rn.f32x2 %0, %1, %2, %0;" : "+l"(*pa) : "l"(bb), "l"(cc));
}

// ---------------- init ----------------
__global__ void k_init(const float* __restrict__ unary, const float* __restrict__ ref,
                       const float* __restrict__ kstd, const float* __restrict__ gk) {
    int t = blockIdx.x * blockDim.x + threadIdx.x;
    if (t < NB * NC * PP) {
        float u = unary[t];
        u = fminf(fmaxf(u, 1e-5f), 1.0f);
        g_U[t] = logf(u);
    }
    if (t < NB * PP) {
        int n = t / PP, p = t % PP;
        int y = p >> 6, x = p & 63;
        float f[5];
        f[0] = (float)y / kstd[0];
        f[1] = (float)x / kstd[1];
        f[2] = ref[(n * 3 + 0) * PP + p] / kstd[2];
        f[3] = ref[(n * 3 + 1) * PP + p] / kstd[3];
        f[4] = ref[(n * 3 + 2) * PP + p] / kstd[4];
        float h = 0.f;
#pragma unroll
        for (int d = 0; d < 5; ++d) {
            g_feat[(n * 5 + d) * PP + p] = f[d];
            h = fmaf(f[d], f[d], h);
        }
        g_h[n * PP + p] = -0.5f * h;
    }
    if (blockIdx.x == 0) {
        __shared__ float s[128];
        int tt = threadIdx.x;
        float v = 0.f;
        if (tt < 128) {
            v = (tt < KS) ? gk[KR * KS + tt] : 0.f;  // channel 0, center row
            s[tt] = v;
        }
        __syncthreads();
        for (int o = 64; o; o >>= 1) {
            if (tt < o && tt + o < 128) s[tt] += s[tt + o];
            __syncthreads();
        }
        if (tt < KS) g_g1d[tt] = v / s[0];
    }
}

// ---------------- build K (symmetric: upper-triangle tiles, smem transpose) ----------------
__global__ void k_buildK() {
    int bj = blockIdx.x, bi = blockIdx.y, n = blockIdx.z;
    if (bj < bi) return;
    __shared__ float sfi[5][64], sfj[5][64], shi[64], shj[64];
    __shared__ float tile[64][65];
    int tid = threadIdx.x;
    if (tid < 64) {
        int pi = bi * 64 + tid, pj = bj * 64 + tid;
#pragma unroll
        for (int d = 0; d < 5; ++d) {
            sfi[d][tid] = g_feat[(n * 5 + d) * PP + pi];
            sfj[d][tid] = g_feat[(n * 5 + d) * PP + pj];
        }
        shi[tid] = g_h[n * PP + pi];
        shj[tid] = g_h[n * PP + pj];
    }
    __syncthreads();
    for (int e = tid; e < 64 * 64; e += 256) {
        int i = e >> 6, j = e & 63;
        float a = shi[i] + shj[j];
#pragma unroll
        for (int d = 0; d < 5; ++d) a = fmaf(sfi[d][i], sfj[d][j], a);
        tile[i][j] = __expf(a);
    }
    __syncthreads();
    size_t base = (size_t)n * PP * PP;
    for (int e = tid; e < 64 * 64; e += 256) {
        int i = e >> 6, j = e & 63;
        g_K[base + (size_t)(bi * 64 + i) * PP + (bj * 64 + j)] = tile[i][j];
    }
    if (bi != bj) {
        for (int e = tid; e < 64 * 64; e += 256) {
            int i = e >> 6, j = e & 63;
            g_K[base + (size_t)(bj * 64 + i) * PP + (bi * 64 + j)] = tile[j][i];
        }
    }
}

// ---------------- fused iteration: GEMM CTAs + spatial-conv CTAs ----------------
// GEMM (coalesced via K symmetry): thread owns 2 output rows p0,p0+1; reads
// K[k][p0..p0+1] as coalesced float2. q comes as channel-pair packed float4
// broadcasts from smem. acc[2][11] packed f32x2 = 44 regs.
__global__ void __launch_bounds__(256, 3) k_iter() {
    __shared__ __align__(16) float s_buf[2 * PP + 128];   // union: gemm sq4 | conv planes

    int tid = threadIdx.x;
    if (blockIdx.x < GEMM_CTAS) {
        int bid = blockIdx.x;
        int n = bid >> 8;
        int rem = bid & 255;
        int rb = rem >> 5;            // rowblock (512 rows each)
        int slice = rem & 31;         // k-slice
        int k0 = slice * KCH;

        // stage packed q chunk: sq4[cp*64+j] = (q2c[k0+2j], q2c1[k0+2j], q2c[k0+2j+1], q2c1[k0+2j+1])
        float4* sq4 = (float4*)s_buf;                       // 704 float4 = 11 KB
        const float4* qp = (const float4*)(g_qpair + (size_t)n * NCP * PP);
        for (int idx = tid; idx < NCP * (KCH / 2); idx += 256) {
            int cp = idx >> 6, j = idx & 63;
            sq4[idx] = qp[cp * (PP / 2) + (k0 >> 1) + j];
        }
        __syncthreads();

        int p0 = rb * 512 + tid * 2;
        const float* Kp = g_K + (size_t)n * PP * PP + (size_t)k0 * PP + p0;

        float2 acc[2][NCP];
#pragma unroll
        for (int r = 0; r < 2; ++r)
#pragma unroll
            for (int cp = 0; cp < NCP; ++cp) acc[r][cp] = make_float2(0.f, 0.f);

#pragma unroll 4
        for (int j = 0; j < KCH / 2; ++j) {
            float2 Ka = *(const float2*)(Kp);         // K[k0+2j][p0..p0+1]
            float2 Kb = *(const float2*)(Kp + PP);    // K[k0+2j+1][p0..p0+1]
            Kp += 2 * PP;
#pragma unroll
            for (int cp = 0; cp < NCP; ++cp) {
                float4 qv = sq4[(cp << 6) + j];
                fma2(acc[0][cp], Ka.x, Ka.x, qv.x, qv.y);
                fma2(acc[0][cp], Kb.x, Kb.x, qv.z, qv.w);
                fma2(acc[1][cp], Ka.y, Ka.y, qv.x, qv.y);
                fma2(acc[1][cp], Kb.y, Kb.y, qv.z, qv.w);
            }
        }

        // coalesced float2 stores: both rows of one channel together
        float* pbase = g_part + (size_t)slice * PP + p0;
#pragma unroll
        for (int cp = 0; cp < NCP; ++cp) {
            *(float2*)(pbase + (size_t)(n * NC + 2 * cp) * KSPL * PP) =
                make_float2(acc[0][cp].x, acc[1][cp].x);
            if (cp < NCP - 1)
                *(float2*)(pbase + (size_t)(n * NC + 2 * cp + 1) * KSPL * PP) =
                    make_float2(acc[0][cp].y, acc[1][cp].y);
        }
    } else {
        // -------- spatial conv (separable 71-tap), one CTA per (n,c) plane --------
        float* sin_ = s_buf;
        float* stmp = s_buf + PP;
        float* sg = s_buf + 2 * PP;
        int cid = blockIdx.x - GEMM_CTAS;
        int c = cid % NC, n = cid / NC;
        if (tid < KS) sg[tid] = g_g1d[tid];
        const float* src = g_q + (n * NC + c) * PP;
        for (int i = tid; i < PP; i += 256) sin_[i] = src[i];
        __syncthreads();
        for (int e = tid; e < PP; e += 256) {
            int y = e >> 6, x = e & 63;
            int lo = max(0, x - KR), hi = min(63, x + KR);
            float a = 0.f;
            for (int xx = lo; xx <= hi; ++xx) a = fmaf(sg[KR + xx - x], sin_[(y << 6) | xx], a);
            stmp[e] = a;
        }
        __syncthreads();
        float* dst = g_qsf + (n * NC + c) * PP;
        for (int e = tid; e < PP; e += 256) {
            int y = e >> 6, x = e & 63;
            int lo = max(0, y - KR), hi = min(63, y + KR);
            float a = 0.f;
            for (int yy = lo; yy <= hi; ++yy) a = fmaf(sg[KR + yy - y], stmp[(yy << 6) | x], a);
            dst[e] = a;
        }
    }
}

// ---------------- reduce k-split partials -> qbf (massively parallel) ----------------
__global__ void k_reduce() {
    int t = blockIdx.x * blockDim.x + threadIdx.x;
    if (t >= NB * NC * PP) return;
    int p = t & 4095, nc = t >> 12;
    const float* pp = g_part + (size_t)nc * KSPL * PP + p;
    float a = 0.f;
#pragma unroll
    for (int s = 0; s < KSPL; ++s) a += pp[s * PP];
    g_qbf[t] = a;
}

// ---------------- softmax / update: q = softmax(U [+ 4*qbf + 2*qsf]) ----------------
__global__ void k_softmax(int usebq, float* __restrict__ extout) {
    int t = blockIdx.x * blockDim.x + threadIdx.x;
    if (t >= NB * PP) return;
    int n = t >> 12, p = t & 4095;
    float v[NC];
    float m = -1e30f;
#pragma unroll
    for (int c = 0; c < NC; ++c) {
        int idx = (n * NC + c) * PP + p;
        float a = g_U[idx];
        if (usebq) a = a + 4.0f * g_qbf[idx] + 2.0f * g_qsf[idx];
        v[c] = a;
        m = fmaxf(m, a);
    }
    float s = 0.f;
#pragma unroll
    for (int c = 0; c < NC; ++c) {
        v[c] = __expf(v[c] - m);
        s += v[c];
    }
    float inv = 1.0f / s;
#pragma unroll
    for (int c = 0; c < NC; ++c) {
        int idx = (n * NC + c) * PP + p;
        float r = v[c] * inv;
        g_q[idx] = r;
        if (extout) extout[idx] = r;
    }
    // packed channel-pair layout for the gemm
#pragma unroll
    for (int cp = 0; cp < NCP; ++cp) {
        float a = v[2 * cp] * inv;
        float b = (2 * cp + 1 < NC) ? v[2 * cp + 1] * inv : 0.f;
        g_qpair[(n * NCP + cp) * PP + p] = make_float2(a, b);
    }
}

// ---------------- launch ----------------
extern "C" void kernel_launch(void* const* d_in, const int* in_sizes, int n_in,
                              void* d_out, int out_size) {
    (void)in_sizes; (void)n_in; (void)out_size;
    const float* unary = (const float*)d_in[0];
    const float* ref   = (const float*)d_in[1];
    const float* gk    = (const float*)d_in[2];
    const float* kstd  = (const float*)d_in[3];
    float* out = (float*)d_out;

    k_init<<<(NB * NC * PP + 255) / 256, 256>>>(unary, ref, kstd, gk);
    k_buildK<<<dim3(64, 64, NB), 256>>>();
    k_softmax<<<64, 128>>>(0, nullptr);  // q0 = softmax(U)

    for (int it = 0; it < 5; ++it) {
        k_iter<<<GEMM_CTAS + CONV_CTAS, 256>>>();
        k_reduce<<<(NB * NC * PP + 255) / 256, 256>>>();
        bool last = (it == 4);
        k_softmax<<<64, 128>>>(1, last ? out : nullptr);
    }
}

// round 10
// speedup vs baseline: 1.0354x; 1.0354x over previous
#include <cuda_runtime.h>
#include <math.h>
#include <stdint.h>

#define NB 2
#define NC 21
#define NCB 32          // padded channel rows for MMA B operand (21..31 stay zero)
#define PP 4096
#define KS 71
#define KR 35
#define KCH 32          // k-chunk in fp32 elems (128 bytes)
#define NCHUNK (PP / KCH)   // 128
#define MMA_CTAS (NB * 64)  // M-tile 64 -> 64 rowblocks per batch
#define CONV_CTAS (NB * NC)
#define ROWPAD 36       // padded smem row stride in floats (bank-conflict-free)
#define ABYTES (64 * ROWPAD * 4)        // 9216
#define BBYTES (NCB * ROWPAD * 4)       // 4608
#define STAGEB (ABYTES + BBYTES)        // 13824
#define NSTAGE 3

// ---------------- scratch (static device globals; zero-initialized) ----------------
__device__ float g_K[(size_t)NB * PP * PP];     // 134 MB fp32, symmetric
__device__ float g_feat[NB * 5 * PP];
__device__ float g_h[NB * PP];
__device__ float g_U[NB * NC * PP];
__device__ float g_qK[NB * NCB * PP];           // q fp32, padded rows 21..31 == 0
__device__ float g_qbf[NB * NC * PP];           // bilateral message (MMA epilogue)
__device__ float g_qsf[NB * NC * PP];           // spatial conv result
__device__ float g_g1d[KS];

// ---------------- PTX helpers ----------------
__device__ __forceinline__ uint32_t smem_u32(const void* p) {
    uint32_t a;
    asm("{ .reg .u64 t; cvta.to.shared.u64 t, %1; cvt.u32.u64 %0, t; }" : "=r"(a) : "l"(p));
    return a;
}
__device__ __forceinline__ uint64_t to_gbl(const void* p) {
    uint64_t r;
    asm("cvta.to.global.u64 %0, %1;" : "=l"(r) : "l"(p));
    return r;
}
__device__ __forceinline__ void cp16(uint32_t s, uint64_t g) {
    asm volatile("cp.async.cg.shared.global [%0], [%1], 16;" :: "r"(s), "l"(g));
}
#define CP_COMMIT() asm volatile("cp.async.commit_group;" ::: "memory")
#define CP_WAIT1()  asm volatile("cp.async.wait_group 1;" ::: "memory")
__device__ __forceinline__ uint32_t f2tf32(float x) {
    uint32_t r;
    asm("cvt.rna.tf32.f32 %0, %1;" : "=r"(r) : "f"(x));
    return r;
}
// split x into tf32 hi + tf32 lo (3xTF32 compensation)
__device__ __forceinline__ void tf32split(float x, uint32_t& hi, uint32_t& lo) {
    hi = f2tf32(x);
    lo = f2tf32(x - __uint_as_float(hi));
}
__device__ __forceinline__ void mma_tf32(float* c, uint32_t a0, uint32_t a1, uint32_t a2,
                                         uint32_t a3, uint32_t b0, uint32_t b1) {
    asm volatile(
        "mma.sync.aligned.m16n8k8.row.col.f32.tf32.tf32.f32 "
        "{%0,%1,%2,%3}, {%4,%5,%6,%7}, {%8,%9}, {%0,%1,%2,%3};"
        : "+f"(c[0]), "+f"(c[1]), "+f"(c[2]), "+f"(c[3])
        : "r"(a0), "r"(a1), "r"(a2), "r"(a3), "r"(b0), "r"(b1));
}

// ---------------- init ----------------
__global__ void k_init(const float* __restrict__ unary, const float* __restrict__ ref,
                       const float* __restrict__ kstd, const float* __restrict__ gk) {
    int t = blockIdx.x * blockDim.x + threadIdx.x;
    if (t < NB * NC * PP) {
        float u = unary[t];
        u = fminf(fmaxf(u, 1e-5f), 1.0f);
        g_U[t] = logf(u);
    }
    if (t < NB * PP) {
        int n = t / PP, p = t % PP;
        int y = p >> 6, x = p & 63;
        float f[5];
        f[0] = (float)y / kstd[0];
        f[1] = (float)x / kstd[1];
        f[2] = ref[(n * 3 + 0) * PP + p] / kstd[2];
        f[3] = ref[(n * 3 + 1) * PP + p] / kstd[3];
        f[4] = ref[(n * 3 + 2) * PP + p] / kstd[4];
        float h = 0.f;
#pragma unroll
        for (int d = 0; d < 5; ++d) {
            g_feat[(n * 5 + d) * PP + p] = f[d];
            h = fmaf(f[d], f[d], h);
        }
        g_h[n * PP + p] = -0.5f * h;
    }
    if (blockIdx.x == 0) {
        __shared__ float s[128];
        int tt = threadIdx.x;
        float v = 0.f;
        if (tt < 128) {
            v = (tt < KS) ? gk[KR * KS + tt] : 0.f;  // channel 0, center row
            s[tt] = v;
        }
        __syncthreads();
        for (int o = 64; o; o >>= 1) {
            if (tt < o && tt + o < 128) s[tt] += s[tt + o];
            __syncthreads();
        }
        if (tt < KS) g_g1d[tt] = v / s[0];
    }
}

// ---------------- build K fp32 (symmetric, upper-triangle tiles) ----------------
__global__ void k_buildK() {
    int bj = blockIdx.x, bi = blockIdx.y, n = blockIdx.z;
    if (bj < bi) return;
    __shared__ float sfi[5][64], sfj[5][64], shi[64], shj[64];
    __shared__ float tile[64][65];
    int tid = threadIdx.x;
    if (tid < 64) {
        int pi = bi * 64 + tid, pj = bj * 64 + tid;
#pragma unroll
        for (int d = 0; d < 5; ++d) {
            sfi[d][tid] = g_feat[(n * 5 + d) * PP + pi];
            sfj[d][tid] = g_feat[(n * 5 + d) * PP + pj];
        }
        shi[tid] = g_h[n * PP + pi];
        shj[tid] = g_h[n * PP + pj];
    }
    __syncthreads();
    for (int e = tid; e < 64 * 64; e += 256) {
        int i = e >> 6, j = e & 63;
        float a = shi[i] + shj[j];
#pragma unroll
        for (int d = 0; d < 5; ++d) a = fmaf(sfi[d][i], sfj[d][j], a);
        tile[i][j] = __expf(a);
    }
    __syncthreads();
    size_t base = (size_t)n * PP * PP;
    for (int e = tid; e < 64 * 64; e += 256) {
        int i = e >> 6, j = e & 63;
        g_K[base + (size_t)(bi * 64 + i) * PP + (bj * 64 + j)] = tile[i][j];
    }
    if (bi != bj) {
        for (int e = tid; e < 64 * 64; e += 256) {
            int i = e >> 6, j = e & 63;
            g_K[base + (size_t)(bj * 64 + i) * PP + (bi * 64 + j)] = tile[j][i];
        }
    }
}

// ---------------- fused iteration: 3xTF32 mma.sync GEMM CTAs + spatial-conv CTAs ----------------
// GEMM: qbf[n][c][p] = sum_k K[n][p][k] * q[n][c][k]. CTA: 4 warps, 64 rows, N=32.
// K streamed in 32-float chunks, cp.async 3-stage pipeline, padded smem rows.
// 3xTF32: acc += ah*bh + al*bh + ah*bl  -> fp32-grade accuracy on tensor cores.
__global__ void __launch_bounds__(128) k_iter() {
    __shared__ __align__(16) unsigned char sbuf[NSTAGE * STAGEB];  // 41472 B

    int tid = threadIdx.x;
    int wid = tid >> 5, lane = tid & 31;

    if (blockIdx.x < MMA_CTAS) {
        int n = blockIdx.x >> 6;
        int rb = blockIdx.x & 63;
        int p0 = rb * 64;

        uint64_t gA = to_gbl(g_K + ((size_t)n * PP + p0) * PP);
        uint64_t gB = to_gbl(g_qK + (size_t)n * NCB * PP);
        uint32_t sb = smem_u32(sbuf);

        auto load_chunk = [&](int c, int st) {
            uint32_t sA = sb + st * STAGEB;
            uint32_t sB = sA + ABYTES;
            uint64_t ga = gA + (uint64_t)c * 128;
            uint64_t gb = gB + (uint64_t)c * 128;
#pragma unroll
            for (int i = 0; i < 4; ++i) {
                int idx = tid + i * 128;           // 0..511
                int row = idx >> 3, un = idx & 7;
                cp16(sA + row * (ROWPAD * 4) + un * 16,
                     ga + (uint64_t)row * (PP * 4) + un * 16);
            }
#pragma unroll
            for (int i = 0; i < 2; ++i) {
                int idx = tid + i * 128;           // 0..255
                int row = idx >> 3, un = idx & 7;
                cp16(sB + row * (ROWPAD * 4) + un * 16,
                     gb + (uint64_t)row * (PP * 4) + un * 16);
            }
        };

        load_chunk(0, 0); CP_COMMIT();
        load_chunk(1, 1); CP_COMMIT();

        int wr = wid * 16;
        int g = lane >> 2, tq = lane & 3;
        float acc[4][4];
#pragma unroll
        for (int nt = 0; nt < 4; ++nt)
#pragma unroll
            for (int r = 0; r < 4; ++r) acc[nt][r] = 0.f;

        for (int c = 0; c < NCHUNK; ++c) {
            CP_WAIT1();
            __syncthreads();
            const float* sA = (const float*)(sbuf + (c % NSTAGE) * STAGEB);
            const float* sB = (const float*)(sbuf + (c % NSTAGE) * STAGEB + ABYTES);
#pragma unroll
            for (int kk = 0; kk < 4; ++kk) {
                int kc = kk * 8 + tq;
                uint32_t a0h, a0l, a1h, a1l, a2h, a2l, a3h, a3l;
                tf32split(sA[(wr + g) * ROWPAD + kc], a0h, a0l);
                tf32split(sA[(wr + g + 8) * ROWPAD + kc], a1h, a1l);
                tf32split(sA[(wr + g) * ROWPAD + kc + 4], a2h, a2l);
                tf32split(sA[(wr + g + 8) * ROWPAD + kc + 4], a3h, a3l);
#pragma unroll
                for (int nt = 0; nt < 4; ++nt) {
                    uint32_t b0h, b0l, b1h, b1l;
                    tf32split(sB[(nt * 8 + g) * ROWPAD + kc], b0h, b0l);
                    tf32split(sB[(nt * 8 + g) * ROWPAD + kc + 4], b1h, b1l);
                    mma_tf32(acc[nt], a0h, a1h, a2h, a3h, b0h, b1h);   // hi*hi
                    mma_tf32(acc[nt], a0l, a1l, a2l, a3l, b0h, b1h);   // lo*hi
                    mma_tf32(acc[nt], a0h, a1h, a2h, a3h, b0l, b1l);   // hi*lo
                }
            }
            __syncthreads();
            if (c + 2 < NCHUNK) load_chunk(c + 2, (c + 2) % NSTAGE);
            CP_COMMIT();
        }

        // epilogue: c0 (row g, col 2tq), c1 (+1), c2 (row g+8), c3 (row g+8, +1)
        int r0 = p0 + wr + g, r1 = r0 + 8;
#pragma unroll
        for (int nt = 0; nt < 4; ++nt) {
            int n0 = nt * 8 + tq * 2;
            if (n0 < NC) {
                g_qbf[(n * NC + n0) * PP + r0] = acc[nt][0];
                g_qbf[(n * NC + n0) * PP + r1] = acc[nt][2];
            }
            if (n0 + 1 < NC) {
                g_qbf[(n * NC + n0 + 1) * PP + r0] = acc[nt][1];
                g_qbf[(n * NC + n0 + 1) * PP + r1] = acc[nt][3];
            }
        }
    } else {
        // -------- spatial conv (separable 71-tap), one CTA per (n,c) plane --------
        float* sin_ = (float*)sbuf;
        float* stmp = sin_ + PP;
        float* sg = stmp + PP;
        int cid = blockIdx.x - MMA_CTAS;
        int c = cid % NC, n = cid / NC;
        if (tid < KS) sg[tid] = g_g1d[tid];
        const float* src = g_qK + (n * NCB + c) * PP;
        for (int i = tid; i < PP; i += 128) sin_[i] = src[i];
        __syncthreads();
        for (int e = tid; e < PP; e += 128) {
            int y = e >> 6, x = e & 63;
            int lo = max(0, x - KR), hi = min(63, x + KR);
            float a = 0.f;
            for (int xx = lo; xx <= hi; ++xx) a = fmaf(sg[KR + xx - x], sin_[(y << 6) | xx], a);
            stmp[e] = a;
        }
        __syncthreads();
        float* dst = g_qsf + (n * NC + c) * PP;
        for (int e = tid; e < PP; e += 128) {
            int y = e >> 6, x = e & 63;
            int lo = max(0, y - KR), hi = min(63, y + KR);
            float a = 0.f;
            for (int yy = lo; yy <= hi; ++yy) a = fmaf(sg[KR + yy - y], stmp[(yy << 6) | x], a);
            dst[e] = a;
        }
    }
}

// ---------------- softmax / update: q = softmax(U [+ 4*qbf + 2*qsf]) ----------------
__global__ void k_softmax(int usebq, float* __restrict__ extout) {
    int t = blockIdx.x * blockDim.x + threadIdx.x;
    if (t >= NB * PP) return;
    int n = t >> 12, p = t & 4095;
    float v[NC];
    float m = -1e30f;
#pragma unroll
    for (int c = 0; c < NC; ++c) {
        int idx = (n * NC + c) * PP + p;
        float a = g_U[idx];
        if (usebq) a = a + 4.0f * g_qbf[idx] + 2.0f * g_qsf[idx];
        v[c] = a;
        m = fmaxf(m, a);
    }
    float s = 0.f;
#pragma unroll
    for (int c = 0; c < NC; ++c) {
        v[c] = __expf(v[c] - m);
        s += v[c];
    }
    float inv = 1.0f / s;
#pragma unroll
    for (int c = 0; c < NC; ++c) {
        float r = v[c] * inv;
        g_qK[(n * NCB + c) * PP + p] = r;
        if (extout) extout[(n * NC + c) * PP + p] = r;
    }
}

// ---------------- launch ----------------
extern "C" void kernel_launch(void* const* d_in, const int* in_sizes, int n_in,
                              void* d_out, int out_size) {
    (void)in_sizes; (void)n_in; (void)out_size;
    const float* unary = (const float*)d_in[0];
    const float* ref   = (const float*)d_in[1];
    const float* gk    = (const float*)d_in[2];
    const float* kstd  = (const float*)d_in[3];
    float* out = (float*)d_out;

    k_init<<<(NB * NC * PP + 255) / 256, 256>>>(unary, ref, kstd, gk);
    k_buildK<<<dim3(64, 64, NB), 256>>>();
    k_softmax<<<64, 128>>>(0, nullptr);  // q0 = softmax(U)

    for (int it = 0; it < 5; ++it) {
        k_iter<<<MMA_CTAS + CONV_CTAS, 128>>>();
        bool last = (it == 4);
        k_softmax<<<64, 128>>>(1, last ? out : nullptr);
    }
}

// round 14
// speedup vs baseline: 1.1073x; 1.0694x over previous
#include <cuda_runtime.h>
#include <math.h>
#include <stdint.h>

#define NB 2
#define NC 21
#define NCB 32          // padded channel rows for MMA B operand (21..31 stay zero)
#define PP 4096
#define KS 71
#define KR 35
#define KSPL 8          // k-split factor
#define KPS (PP / KSPL) // 512 k per slice
#define KCH 32          // k-chunk in fp32 elems
#define NCHL (KPS / KCH)    // 16 local chunks
#define MMA_CTAS (NB * 64 * KSPL)   // 1024
#define CONV_CTAS (NB * NC)
#define ROWPAD 36       // padded smem row stride in floats
#define ABYTES (64 * ROWPAD * 4)        // 9216
#define BBYTES (NCB * ROWPAD * 4)       // 4608
#define STAGEB (ABYTES + BBYTES)        // 13824
#define PSPL_OFF (2 * STAGEB)           // presplit B buffers offset
#define SMEM_BYTES (PSPL_OFF + 2 * BBYTES)  // 36864 (also covers conv's 33 KB)

// ---------------- scratch (static device globals; zero-initialized) ----------------
__device__ float g_K[(size_t)NB * PP * PP];     // 134 MB fp32, symmetric
__device__ float g_feat[NB * 5 * PP];
__device__ float g_h[NB * PP];
__device__ float g_U[NB * NC * PP];
__device__ float g_qK[NB * NCB * PP];           // q fp32, padded rows 21..31 == 0
__device__ float g_part[NB * NC * KSPL * PP];   // gemm k-split partials (5.5 MB)
__device__ float g_qbf[NB * NC * PP];           // reduced bilateral message
__device__ float g_qsf[NB * NC * PP];           // spatial conv result
__device__ float g_g1d[KS];

// ---------------- PTX helpers ----------------
__device__ __forceinline__ uint32_t smem_u32(const void* p) {
    uint32_t a;
    asm("{ .reg .u64 t; cvta.to.shared.u64 t, %1; cvt.u32.u64 %0, t; }" : "=r"(a) : "l"(p));
    return a;
}
__device__ __forceinline__ uint64_t to_gbl(const void* p) {
    uint64_t r;
    asm("cvta.to.global.u64 %0, %1;" : "=l"(r) : "l"(p));
    return r;
}
__device__ __forceinline__ void cp16(uint32_t s, uint64_t g) {
    asm volatile("cp.async.cg.shared.global [%0], [%1], 16;" :: "r"(s), "l"(g));
}
#define CP_COMMIT() asm volatile("cp.async.commit_group;" ::: "memory")
#define CP_WAIT1()  asm volatile("cp.async.wait_group 1;" ::: "memory")
__device__ __forceinline__ uint32_t f2tf32(float x) {
    uint32_t r;
    asm("cvt.rna.tf32.f32 %0, %1;" : "=r"(r) : "f"(x));
    return r;
}
__device__ __forceinline__ void tf32split(float x, uint32_t& hi, uint32_t& lo) {
    hi = f2tf32(x);
    lo = f2tf32(x - __uint_as_float(hi));
}
__device__ __forceinline__ void mma_tf32(float* c, uint32_t a0, uint32_t a1, uint32_t a2,
                                         uint32_t a3, uint32_t b0, uint32_t b1) {
    asm volatile(
        "mma.sync.aligned.m16n8k8.row.col.f32.tf32.tf32.f32 "
        "{%0,%1,%2,%3}, {%4,%5,%6,%7}, {%8,%9}, {%0,%1,%2,%3};"
        : "+f"(c[0]), "+f"(c[1]), "+f"(c[2]), "+f"(c[3])
        : "r"(a0), "r"(a1), "r"(a2), "r"(a3), "r"(b0), "r"(b1));
}

// ---------------- init ----------------
__global__ void k_init(const float* __restrict__ unary, const float* __restrict__ ref,
                       const float* __restrict__ kstd, const float* __restrict__ gk) {
    int t = blockIdx.x * blockDim.x + threadIdx.x;
    if (t < NB * NC * PP) {
        float u = unary[t];
        u = fminf(fmaxf(u, 1e-5f), 1.0f);
        g_U[t] = logf(u);
    }
    if (t < NB * PP) {
        int n = t / PP, p = t % PP;
        int y = p >> 6, x = p & 63;
        float f[5];
        f[0] = (float)y / kstd[0];
        f[1] = (float)x / kstd[1];
        f[2] = ref[(n * 3 + 0) * PP + p] / kstd[2];
        f[3] = ref[(n * 3 + 1) * PP + p] / kstd[3];
        f[4] = ref[(n * 3 + 2) * PP + p] / kstd[4];
        float h = 0.f;
#pragma unroll
        for (int d = 0; d < 5; ++d) {
            g_feat[(n * 5 + d) * PP + p] = f[d];
            h = fmaf(f[d], f[d], h);
        }
        g_h[n * PP + p] = -0.5f * h;
    }
    if (blockIdx.x == 0) {
        __shared__ float s[128];
        int tt = threadIdx.x;
        float v = 0.f;
        if (tt < 128) {
            v = (tt < KS) ? gk[KR * KS + tt] : 0.f;  // channel 0, center row
            s[tt] = v;
        }
        __syncthreads();
        for (int o = 64; o; o >>= 1) {
            if (tt < o && tt + o < 128) s[tt] += s[tt + o];
            __syncthreads();
        }
        if (tt < KS) g_g1d[tt] = v / s[0];
    }
}

// ---------------- build K fp32 (symmetric, upper-triangle tiles) ----------------
__global__ void k_buildK() {
    int bj = blockIdx.x, bi = blockIdx.y, n = blockIdx.z;
    if (bj < bi) return;
    __shared__ float sfi[5][64], sfj[5][64], shi[64], shj[64];
    __shared__ float tile[64][65];
    int tid = threadIdx.x;
    if (tid < 64) {
        int pi = bi * 64 + tid, pj = bj * 64 + tid;
#pragma unroll
        for (int d = 0; d < 5; ++d) {
            sfi[d][tid] = g_feat[(n * 5 + d) * PP + pi];
            sfj[d][tid] = g_feat[(n * 5 + d) * PP + pj];
        }
        shi[tid] = g_h[n * PP + pi];
        shj[tid] = g_h[n * PP + pj];
    }
    __syncthreads();
    for (int e = tid; e < 64 * 64; e += 256) {
        int i = e >> 6, j = e & 63;
        float a = shi[i] + shj[j];
#pragma unroll
        for (int d = 0; d < 5; ++d) a = fmaf(sfi[d][i], sfj[d][j], a);
        tile[i][j] = __expf(a);
    }
    __syncthreads();
    size_t base = (size_t)n * PP * PP;
    for (int e = tid; e < 64 * 64; e += 256) {
        int i = e >> 6, j = e & 63;
        g_K[base + (size_t)(bi * 64 + i) * PP + (bj * 64 + j)] = tile[i][j];
    }
    if (bi != bj) {
        for (int e = tid; e < 64 * 64; e += 256) {
            int i = e >> 6, j = e & 63;
            g_K[base + (size_t)(bj * 64 + i) * PP + (bi * 64 + j)] = tile[j][i];
        }
    }
}

// ---------------- fused iteration: 3xTF32 mma.sync GEMM (k-split) + spatial-conv ----------------
// GEMM CTA: 4 warps, 64 rows, N=32, k-slice of 512. 2-stage cp.async pipeline.
// B operand pre-split to tf32 hi/lo in smem once per chunk (kills redundant cvt ALU).
__global__ void __launch_bounds__(128) k_iter() {
    __shared__ __align__(16) unsigned char sbuf[SMEM_BYTES];

    int tid = threadIdx.x;
    int wid = tid >> 5, lane = tid & 31;

    if (blockIdx.x < MMA_CTAS) {
        int bid = blockIdx.x;
        int n = bid >> 9;
        int rem = bid & 511;
        int rb = rem >> 3;            // rowblock 0..63
        int slice = rem & 7;          // k-slice 0..7
        int p0 = rb * 64;
        int k0 = slice * KPS;

        uint64_t gA = to_gbl(g_K + ((size_t)n * PP + p0) * PP + k0);
        uint64_t gB = to_gbl(g_qK + (size_t)n * NCB * PP + k0);
        uint32_t sb = smem_u32(sbuf);

        auto load_chunk = [&](int c, int st) {
            uint32_t sA = sb + st * STAGEB;
            uint32_t sB = sA + ABYTES;
            uint64_t ga = gA + (uint64_t)c * 128;
            uint64_t gb = gB + (uint64_t)c * 128;
#pragma unroll
            for (int i = 0; i < 4; ++i) {
                int idx = tid + i * 128;           // 0..511
                int row = idx >> 3, un = idx & 7;
                cp16(sA + row * (ROWPAD * 4) + un * 16,
                     ga + (uint64_t)row * (PP * 4) + un * 16);
            }
#pragma unroll
            for (int i = 0; i < 2; ++i) {
                int idx = tid + i * 128;           // 0..255
                int row = idx >> 3, un = idx & 7;
                cp16(sB + row * (ROWPAD * 4) + un * 16,
                     gb + (uint64_t)row * (PP * 4) + un * 16);
            }
        };

        load_chunk(0, 0); CP_COMMIT();

        int wr = wid * 16;
        int g = lane >> 2, tq = lane & 3;
        float acc[4][4];
#pragma unroll
        for (int nt = 0; nt < 4; ++nt)
#pragma unroll
            for (int r = 0; r < 4; ++r) acc[nt][r] = 0.f;

        uint32_t* Bh = (uint32_t*)(sbuf + PSPL_OFF);
        uint32_t* Bl = Bh + NCB * ROWPAD;

        for (int c = 0; c < NCHL; ++c) {
            if (c + 1 < NCHL) load_chunk(c + 1, (c + 1) & 1);
            CP_COMMIT();
            CP_WAIT1();
            __syncthreads();
            const float* sA = (const float*)(sbuf + (c & 1) * STAGEB);
            const float* sB = (const float*)(sbuf + (c & 1) * STAGEB + ABYTES);
            // presplit B chunk (32 rows x 32 cols) once, cooperatively
#pragma unroll
            for (int i = 0; i < 8; ++i) {
                int e = tid + i * 128;             // 0..1023
                int row = e >> 5, col = e & 31;
                float v = sB[row * ROWPAD + col];
                uint32_t h = f2tf32(v);
                Bh[row * ROWPAD + col] = h;
                Bl[row * ROWPAD + col] = f2tf32(v - __uint_as_float(h));
            }
            __syncthreads();
#pragma unroll
            for (int kk = 0; kk < 4; ++kk) {
                int kc = kk * 8 + tq;
                uint32_t a0h, a0l, a1h, a1l, a2h, a2l, a3h, a3l;
                tf32split(sA[(wr + g) * ROWPAD + kc], a0h, a0l);
                tf32split(sA[(wr + g + 8) * ROWPAD + kc], a1h, a1l);
                tf32split(sA[(wr + g) * ROWPAD + kc + 4], a2h, a2l);
                tf32split(sA[(wr + g + 8) * ROWPAD + kc + 4], a3h, a3l);
#pragma unroll
                for (int nt = 0; nt < 4; ++nt) {
                    int br = (nt * 8 + g) * ROWPAD;
                    uint32_t b0h = Bh[br + kc], b1h = Bh[br + kc + 4];
                    uint32_t b0l = Bl[br + kc], b1l = Bl[br + kc + 4];
                    mma_tf32(acc[nt], a0h, a1h, a2h, a3h, b0h, b1h);   // hi*hi
                    mma_tf32(acc[nt], a0l, a1l, a2l, a3l, b0h, b1h);   // lo*hi
                    mma_tf32(acc[nt], a0h, a1h, a2h, a3h, b0l, b1l);   // hi*lo
                }
            }
            __syncthreads();
        }

        // epilogue -> k-split partials
        int r0 = p0 + wr + g, r1 = r0 + 8;
#pragma unroll
        for (int nt = 0; nt < 4; ++nt) {
            int n0 = nt * 8 + tq * 2;
            if (n0 < NC) {
                float* d = g_part + ((size_t)(n * NC + n0) * KSPL + slice) * PP;
                d[r0] = acc[nt][0];
                d[r1] = acc[nt][2];
            }
            if (n0 + 1 < NC) {
                float* d = g_part + ((size_t)(n * NC + n0 + 1) * KSPL + slice) * PP;
                d[r0] = acc[nt][1];
                d[r1] = acc[nt][3];
            }
        }
    } else {
        // -------- spatial conv (separable 71-tap), one CTA per (n,c) plane --------
        float* sin_ = (float*)sbuf;
        float* stmp = sin_ + PP;
        float* sg = stmp + PP;
        int cid = blockIdx.x - MMA_CTAS;
        int c = cid % NC, n = cid / NC;
        if (tid < KS) sg[tid] = g_g1d[tid];
        const float* src = g_qK + (n * NCB + c) * PP;
        for (int i = tid; i < PP; i += 128) sin_[i] = src[i];
        __syncthreads();
        for (int e = tid; e < PP; e += 128) {
            int y = e >> 6, x = e & 63;
            int lo = max(0, x - KR), hi = min(63, x + KR);
            float a = 0.f;
            for (int xx = lo; xx <= hi; ++xx) a = fmaf(sg[KR + xx - x], sin_[(y << 6) | xx], a);
            stmp[e] = a;
        }
        __syncthreads();
        float* dst = g_qsf + (n * NC + c) * PP;
        for (int e = tid; e < PP; e += 128) {
            int y = e >> 6, x = e & 63;
            int lo = max(0, y - KR), hi = min(63, y + KR);
            float a = 0.f;
            for (int yy = lo; yy <= hi; ++yy) a = fmaf(sg[KR + yy - y], stmp[(yy << 6) | x], a);
            dst[e] = a;
        }
    }
}

// ---------------- reduce k-split partials -> qbf (coalesced) ----------------
__global__ void k_reduce() {
    int t = blockIdx.x * blockDim.x + threadIdx.x;
    if (t >= NB * NC * PP) return;
    int p = t & 4095, nc = t >> 12;
    const float* pp = g_part + (size_t)nc * KSPL * PP + p;
    float a = 0.f;
#pragma unroll
    for (int s = 0; s < KSPL; ++s) a += pp[s * PP];
    g_qbf[t] = a;
}

// ---------------- softmax / update: q = softmax(U [+ 4*qbf + 2*qsf]) ----------------
__global__ void k_softmax(int usebq, float* __restrict__ extout) {
    int t = blockIdx.x * blockDim.x + threadIdx.x;
    if (t >= NB * PP) return;
    int n = t >> 12, p = t & 4095;
    float v[NC];
    float m = -1e30f;
#pragma unroll
    for (int c = 0; c < NC; ++c) {
        int idx = (n * NC + c) * PP + p;
        float a = g_U[idx];
        if (usebq) a = a + 4.0f * g_qbf[idx] + 2.0f * g_qsf[idx];
        v[c] = a;
        m = fmaxf(m, a);
    }
    float s = 0.f;
#pragma unroll
    for (int c = 0; c < NC; ++c) {
        v[c] = __expf(v[c] - m);
        s += v[c];
    }
    float inv = 1.0f / s;
#pragma unroll
    for (int c = 0; c < NC; ++c) {
        float r = v[c] * inv;
        g_qK[(n * NCB + c) * PP + p] = r;
        if (extout) extout[(n * NC + c) * PP + p] = r;
    }
}

// ---------------- launch ----------------
extern "C" void kernel_launch(void* const* d_in, const int* in_sizes, int n_in,
                              void* d_out, int out_size) {
    (void)in_sizes; (void)n_in; (void)out_size;
    const float* unary = (const float*)d_in[0];
    const float* ref   = (const float*)d_in[1];
    const float* gk    = (const float*)d_in[2];
    const float* kstd  = (const float*)d_in[3];
    float* out = (float*)d_out;

    k_init<<<(NB * NC * PP + 255) / 256, 256>>>(unary, ref, kstd, gk);
    k_buildK<<<dim3(64, 64, NB), 256>>>();
    k_softmax<<<64, 128>>>(0, nullptr);  // q0 = softmax(U)

    for (int it = 0; it < 5; ++it) {
        k_iter<<<MMA_CTAS + CONV_CTAS, 128>>>();
        k_reduce<<<(NB * NC * PP + 255) / 256, 256>>>();
        bool last = (it == 4);
        k_softmax<<<64, 128>>>(1, last ? out : nullptr);
    }
}